// round 7
// baseline (speedup 1.0000x reference)
#include <cuda_runtime.h>
#include <cuda_bf16.h>
#include <cstdint>

// VSC3x3Rulebook on GB300 — HMMA bf16-split + TMA bulk-reduce scatter.
//   out = scatter_add_{k,m}( feats[in_rows[k,m]] @ weight[k] -> out_rows[k,m] ) + bias
//   d_out (float32): [ float(coords) | out[N,64] ]

#define TILE_E 128
#define GRID_X 32

// dynamic smem layout (16B aligned base; all offsets 16B multiples)
#define WLO_OFF 0          // 64 x 144B  : bf16 W_lo, [co][ci]
#define AHI_OFF 9216       // 128 x 144B : bf16 A_hi
#define ALO_OFF 27648      // 128 x 144B : bf16 A_lo
#define STG_OFF 46080      // 128 x 272B : f32 D stage (68-float stride)
#define SMEM_SZ 80896

// ---- merged prep: bias-init of out + coords int->float cast (both float4) ----
__global__ void vsc_prep(float4* __restrict__ out4,
                         const float4* __restrict__ bias4, int total4,
                         const int4* __restrict__ coords4,
                         float4* __restrict__ outc4, int nc4) {
    int idx = blockIdx.x * blockDim.x + threadIdx.x;
    if (idx < total4) {
        out4[idx] = bias4[idx & 15];
    } else {
        int j = idx - total4;
        if (j < nc4) {
            int4 v = coords4[j];
            outc4[j] = make_float4((float)v.x, (float)v.y, (float)v.z, (float)v.w);
        }
    }
}

__device__ __forceinline__ uint2 bf16split2(float a, float b) {
    __nv_bfloat16 ha = __float2bfloat16(a);
    __nv_bfloat16 hb = __float2bfloat16(b);
    __nv_bfloat16 la = __float2bfloat16(a - __bfloat162float(ha));
    __nv_bfloat16 lb = __float2bfloat16(b - __bfloat162float(hb));
    uint2 r;
    r.x = (uint32_t)__bfloat16_as_ushort(ha) | ((uint32_t)__bfloat16_as_ushort(hb) << 16);
    r.y = (uint32_t)__bfloat16_as_ushort(la) | ((uint32_t)__bfloat16_as_ushort(lb) << 16);
    return r;
}

__device__ __forceinline__ void mma16816(float* c, const uint32_t* a,
                                         uint32_t b0, uint32_t b1) {
    asm volatile(
        "mma.sync.aligned.m16n8k16.row.col.f32.bf16.bf16.f32 "
        "{%0,%1,%2,%3}, {%4,%5,%6,%7}, {%8,%9}, {%0,%1,%2,%3};"
        : "+f"(c[0]), "+f"(c[1]), "+f"(c[2]), "+f"(c[3])
        : "r"(a[0]), "r"(a[1]), "r"(a[2]), "r"(a[3]), "r"(b0), "r"(b1));
}

#define LDMX4(r, addr)                                                     \
    asm volatile("ldmatrix.sync.aligned.m8n8.x4.shared.b16 "               \
                 "{%0,%1,%2,%3}, [%4];"                                    \
                 : "=r"((r)[0]), "=r"((r)[1]), "=r"((r)[2]), "=r"((r)[3])  \
                 : "r"(addr))
#define LDMX2(r0, r1, addr)                                                \
    asm volatile("ldmatrix.sync.aligned.m8n8.x2.shared.b16 "               \
                 "{%0,%1}, [%2];"                                          \
                 : "=r"(r0), "=r"(r1) : "r"(addr))

__global__ __launch_bounds__(256, 2) void vsc_mma(
    const float* __restrict__ feats,
    const int*   __restrict__ in_rows,
    const int*   __restrict__ out_rows,
    const float* __restrict__ weight,
    float*       __restrict__ out,
    int M, int ntiles)
{
    extern __shared__ __align__(16) char smem[];
    const uint32_t sb = (uint32_t)__cvta_generic_to_shared(smem);

    const int tid   = threadIdx.x;
    const int w     = tid >> 5;
    const int l     = tid & 31;
    const int eslab = w >> 1;    // 0..3 : 32-entry slab
    const int nhalf = w & 1;     // 0/1  : output-column half
    const int k     = blockIdx.y;
    const long kM   = (long)k * M;
    const float* Wg = weight + (size_t)k * 4096;   // [ci][co]

    // ---- W_lo -> smem [co][ci], 144B rows ----
    for (int i = tid; i < 4096; i += 256) {
        const int n = i >> 6, ci = i & 63;
        const float v = Wg[(size_t)ci * 64 + n];
        const float lo = v - __bfloat162float(__float2bfloat16(v));
        *reinterpret_cast<__nv_bfloat16*>(smem + WLO_OFF + n * 144 + ci * 2) =
            __float2bfloat16(lo);
    }

    // ---- W_hi fragments -> registers ----
    uint32_t Bhi[4][4][2];
    {
        const int n = nhalf * 32 + (l >> 2);
        #pragma unroll
        for (int nt = 0; nt < 4; nt++)
            #pragma unroll
            for (int ks = 0; ks < 4; ks++)
                #pragma unroll
                for (int j = 0; j < 2; j++) {
                    const int ci0 = ks * 16 + j * 8 + 2 * (l & 3);
                    const float w0 = Wg[(size_t)ci0 * 64 + n + nt * 8];
                    const float w1 = Wg[(size_t)(ci0 + 1) * 64 + n + nt * 8];
                    Bhi[nt][ks][j] =
                        (uint32_t)__bfloat16_as_ushort(__float2bfloat16(w0))
                      | ((uint32_t)__bfloat16_as_ushort(__float2bfloat16(w1)) << 16);
                }
    }
    __syncthreads();

    const uint32_t a_row = (l & 7) + ((l >> 3) & 1) * 8;
    const uint32_t a_kof = (l >> 4) * 8;
    const uint32_t b_row = nhalf * 32 + (l & 7);
    const uint32_t b_kof = ((l >> 3) & 1) * 8;

    const int er = tid >> 3;
    const int g8 = tid & 7;

    // ---- prefetch rulebook indices for the first tile ----
    int irw[4], orw = 0;
    {
        const int ebase = blockIdx.x * TILE_E;
        #pragma unroll
        for (int p = 0; p < 4; p++) {
            int eg = ebase + p * 32 + er;
            if (eg >= M) eg = M - 1;
            irw[p] = __ldg(in_rows + kM + eg);
        }
        if (tid < TILE_E) {
            int eg = ebase + tid;
            orw = (eg < M) ? __ldg(out_rows + kM + eg) : -1;
        }
    }

    for (int tile = blockIdx.x; tile < ntiles; tile += GRID_X) {
        const int ebase = tile * TILE_E;

        // ---- gather + split + STS (A buffers; stage untouched) ----
        #pragma unroll
        for (int p = 0; p < 4; p++) {
            const int e = p * 32 + er;
            const float4* fp = reinterpret_cast<const float4*>(
                feats + (size_t)irw[p] * 64 + g8 * 8);
            const float4 v0 = __ldg(fp);
            const float4 v1 = __ldg(fp + 1);
            const uint2 p0 = bf16split2(v0.x, v0.y);
            const uint2 p1 = bf16split2(v0.z, v0.w);
            const uint2 p2 = bf16split2(v1.x, v1.y);
            const uint2 p3 = bf16split2(v1.z, v1.w);
            const int off = e * 144 + g8 * 16;
            *reinterpret_cast<uint4*>(smem + AHI_OFF + off) =
                make_uint4(p0.x, p1.x, p2.x, p3.x);
            *reinterpret_cast<uint4*>(smem + ALO_OFF + off) =
                make_uint4(p0.y, p1.y, p2.y, p3.y);
        }

        // ---- prefetch next tile's indices (off critical path) ----
        const int orw_cur = orw;
        {
            const int nbase = ebase + GRID_X * TILE_E;
            if (nbase < ntiles * TILE_E) {
                #pragma unroll
                for (int p = 0; p < 4; p++) {
                    int eg = nbase + p * 32 + er;
                    if (eg >= M) eg = M - 1;
                    irw[p] = __ldg(in_rows + kM + eg);
                }
                if (tid < TILE_E) {
                    int eg = nbase + tid;
                    orw = (eg < M) ? __ldg(out_rows + kM + eg) : -1;
                }
            }
        }
        __syncthreads();

        // ---- compute ----
        float acc[2][4][4];
        #pragma unroll
        for (int s = 0; s < 2; s++)
            #pragma unroll
            for (int nt = 0; nt < 4; nt++)
                #pragma unroll
                for (int r = 0; r < 4; r++) acc[s][nt][r] = 0.f;

        #pragma unroll
        for (int ks = 0; ks < 4; ks++) {
            uint32_t blo[4][2];
            #pragma unroll
            for (int nt = 0; nt < 4; nt++) {
                const uint32_t ba = sb + WLO_OFF
                    + (b_row + nt * 8) * 144 + (ks * 16 + b_kof) * 2;
                LDMX2(blo[nt][0], blo[nt][1], ba);
            }
            #pragma unroll
            for (int s = 0; s < 2; s++) {
                const uint32_t ao =
                    (eslab * 32 + s * 16 + a_row) * 144 + (ks * 16 + a_kof) * 2;
                uint32_t ahi[4], alo[4];
                LDMX4(ahi, sb + AHI_OFF + ao);
                LDMX4(alo, sb + ALO_OFF + ao);
                #pragma unroll
                for (int nt = 0; nt < 4; nt++) {
                    mma16816(acc[s][nt], ahi, Bhi[nt][ks][0], Bhi[nt][ks][1]);
                    mma16816(acc[s][nt], ahi, blo[nt][0],     blo[nt][1]);
                    mma16816(acc[s][nt], alo, Bhi[nt][ks][0], Bhi[nt][ks][1]);
                }
            }
        }

        // ---- drain previous tile's bulk reduces, then restage ----
        asm volatile("cp.async.bulk.wait_group 0;" ::: "memory");
        __syncthreads();   // stage free; also all warps past ldmatrix

        {
            const int r0 = l >> 2;            // 0..7
            const int cb = 2 * (l & 3);       // 0,2,4,6
            float* stg = reinterpret_cast<float*>(smem + STG_OFF);
            #pragma unroll
            for (int s = 0; s < 2; s++) {
                const int eb = eslab * 32 + s * 16;
                #pragma unroll
                for (int nt = 0; nt < 4; nt++) {
                    const int c = nhalf * 32 + nt * 8 + cb;
                    *reinterpret_cast<float2*>(&stg[(eb + r0) * 68 + c]) =
                        make_float2(acc[s][nt][0], acc[s][nt][1]);
                    *reinterpret_cast<float2*>(&stg[(eb + r0 + 8) * 68 + c]) =
                        make_float2(acc[s][nt][2], acc[s][nt][3]);
                }
            }
        }
        asm volatile("fence.proxy.async.shared::cta;" ::: "memory");
        __syncthreads();

        // ---- one 256B bulk reduce-add per entry ----
        if (tid < TILE_E && orw_cur >= 0) {
            const float* dst = out + (size_t)orw_cur * 64;
            const uint32_t src = sb + STG_OFF + tid * 272;
            asm volatile(
                "cp.reduce.async.bulk.global.shared::cta.bulk_group.add.f32 "
                "[%0], [%1], 256;"
                :: "l"(dst), "r"(src) : "memory");
        }
        asm volatile("cp.async.bulk.commit_group;" ::: "memory");
        // no sync: next gather writes A buffers only; stage protected by
        // wait_group + sync at the top of the next epilogue.
    }

    asm volatile("cp.async.bulk.wait_group 0;" ::: "memory");
}

extern "C" void kernel_launch(void* const* d_in, const int* in_sizes, int n_in,
                              void* d_out, int out_size) {
    const int*   coords   = (const int*)  d_in[0];
    const float* feats    = (const float*)d_in[1];
    const int*   in_rows  = (const int*)  d_in[2];
    const int*   out_rows = (const int*)  d_in[3];
    const float* weight   = (const float*)d_in[4];
    const float* bias     = (const float*)d_in[5];

    const int N = in_sizes[1] / 64;   // feats is [N, 64]
    const int M = in_sizes[2] / 9;    // in_rows is [9, M]

    // d_out is float32: [ float(coords) | out[N,64] ]
    float* outf = (float*)d_out;
    long coords_elems = (long)out_size - (long)N * 64;
    if (coords_elems < 0) coords_elems = 0;
    if (coords_elems > in_sizes[0]) coords_elems = in_sizes[0];
    float* out = outf + coords_elems;

    const int total4 = N * 16;                    // out floats / 4
    const int nc4    = (int)(coords_elems / 4);   // coords: N*3 divisible by 4
    const int tot    = total4 + nc4;
    vsc_prep<<<(tot + 255) / 256, 256>>>(
        (float4*)out, (const float4*)bias, total4,
        (const int4*)coords, (float4*)outf, nc4);

    cudaFuncSetAttribute(vsc_mma, cudaFuncAttributeMaxDynamicSharedMemorySize,
                         SMEM_SZ);
    const int ntiles = (M + TILE_E - 1) / TILE_E;
    dim3 grid(GRID_X, 9);
    vsc_mma<<<grid, 256, SMEM_SZ>>>(feats, in_rows, out_rows, weight, out,
                                    M, ntiles);
}

// round 8
// speedup vs baseline: 1.1106x; 1.1106x over previous
#include <cuda_runtime.h>
#include <cuda_bf16.h>
#include <cstdint>

// VSC3x3Rulebook on GB300 — HMMA bf16-split, double-buffered gather overlap,
// TMA bulk-reduce scatter.
//   out = scatter_add_{k,m}( feats[in_rows[k,m]] @ weight[k] -> out_rows[k,m] ) + bias
//   d_out (float32): [ float(coords) | out[N,64] ]

#define TILE_E 128
#define GRID_X 32

// XOR swizzle on 128B-stride tiles (SW128 pattern)
#define SW(o) ((o) ^ (((o) >> 3) & 0x70))

// smem layout from 1024-aligned base
#define WLO_OFF 0                       // 64 x 128B bf16 W_lo [co][ci], swizzled
#define AHI(b) (8192 + (b) * 32768)     // 128 x 128B bf16 A_hi, swizzled
#define ALO(b) (8192 + (b) * 32768 + 16384)
#define STG_OFF 73728                   // 128 x 272B f32 D stage
#define SMEM_SZ (108544 + 1024)

// ---- merged prep: bias-init of out + coords int->float cast ----
__global__ void vsc_prep(float4* __restrict__ out4,
                         const float4* __restrict__ bias4, int total4,
                         const int4* __restrict__ coords4,
                         float4* __restrict__ outc4, int nc4) {
    int idx = blockIdx.x * blockDim.x + threadIdx.x;
    if (idx < total4) {
        out4[idx] = bias4[idx & 15];
    } else {
        int j = idx - total4;
        if (j < nc4) {
            int4 v = coords4[j];
            outc4[j] = make_float4((float)v.x, (float)v.y, (float)v.z, (float)v.w);
        }
    }
}

__device__ __forceinline__ uint2 bf16split2(float a, float b) {
    __nv_bfloat16 ha = __float2bfloat16(a);
    __nv_bfloat16 hb = __float2bfloat16(b);
    __nv_bfloat16 la = __float2bfloat16(a - __bfloat162float(ha));
    __nv_bfloat16 lb = __float2bfloat16(b - __bfloat162float(hb));
    uint2 r;
    r.x = (uint32_t)__bfloat16_as_ushort(ha) | ((uint32_t)__bfloat16_as_ushort(hb) << 16);
    r.y = (uint32_t)__bfloat16_as_ushort(la) | ((uint32_t)__bfloat16_as_ushort(lb) << 16);
    return r;
}

__device__ __forceinline__ void mma16816(float* c, const uint32_t* a,
                                         uint32_t b0, uint32_t b1) {
    asm volatile(
        "mma.sync.aligned.m16n8k16.row.col.f32.bf16.bf16.f32 "
        "{%0,%1,%2,%3}, {%4,%5,%6,%7}, {%8,%9}, {%0,%1,%2,%3};"
        : "+f"(c[0]), "+f"(c[1]), "+f"(c[2]), "+f"(c[3])
        : "r"(a[0]), "r"(a[1]), "r"(a[2]), "r"(a[3]), "r"(b0), "r"(b1));
}

#define LDMX4(r, addr)                                                     \
    asm volatile("ldmatrix.sync.aligned.m8n8.x4.shared.b16 "               \
                 "{%0,%1,%2,%3}, [%4];"                                    \
                 : "=r"((r)[0]), "=r"((r)[1]), "=r"((r)[2]), "=r"((r)[3])  \
                 : "r"(addr))
#define LDMX2(r0, r1, addr)                                                \
    asm volatile("ldmatrix.sync.aligned.m8n8.x2.shared.b16 "               \
                 "{%0,%1}, [%2];"                                          \
                 : "=r"(r0), "=r"(r1) : "r"(addr))

// convert + store one gathered pass (32 entries x 8 ci-octets) into buffer b
__device__ __forceinline__ void sts_pass(char* smem, int b, int e, int g8,
                                         const float4 v0, const float4 v1) {
    const uint2 p0 = bf16split2(v0.x, v0.y);
    const uint2 p1 = bf16split2(v0.z, v0.w);
    const uint2 p2 = bf16split2(v1.x, v1.y);
    const uint2 p3 = bf16split2(v1.z, v1.w);
    const unsigned off = (unsigned)e * 128 + (unsigned)g8 * 16;
    const unsigned sw  = SW(off);
    *reinterpret_cast<uint4*>(smem + AHI(b) + sw) = make_uint4(p0.x, p1.x, p2.x, p3.x);
    *reinterpret_cast<uint4*>(smem + ALO(b) + sw) = make_uint4(p0.y, p1.y, p2.y, p3.y);
}

__global__ __launch_bounds__(256, 2) void vsc_mma(
    const float* __restrict__ feats,
    const int*   __restrict__ in_rows,
    const int*   __restrict__ out_rows,
    const float* __restrict__ weight,
    float*       __restrict__ out,
    int M, int ntiles)
{
    extern __shared__ __align__(16) char dsm[];
    const uint32_t raw = (uint32_t)__cvta_generic_to_shared(dsm);
    const uint32_t sb  = (raw + 1023u) & ~1023u;
    char* smem = dsm + (sb - raw);

    const int tid   = threadIdx.x;
    const int w     = tid >> 5;
    const int l     = tid & 31;
    const int eslab = w >> 1;    // 0..3 : 32-entry slab
    const int nhalf = w & 1;     // 0/1  : output-column half
    const int k     = blockIdx.y;
    const long kM   = (long)k * M;
    const float* Wg = weight + (size_t)k * 4096;   // [ci][co]

    // ---- W_lo -> smem [co][ci], 128B rows, swizzled ----
    for (int i = tid; i < 4096; i += 256) {
        const int n = i >> 6, ci = i & 63;
        const float v = Wg[(size_t)ci * 64 + n];
        const float lo = v - __bfloat162float(__float2bfloat16(v));
        const unsigned off = (unsigned)n * 128 + (unsigned)ci * 2;
        *reinterpret_cast<__nv_bfloat16*>(smem + WLO_OFF + SW(off)) =
            __float2bfloat16(lo);
    }

    // ---- W_hi fragments -> registers ----
    uint32_t Bhi[4][4][2];
    {
        const int n = nhalf * 32 + (l >> 2);
        #pragma unroll
        for (int nt = 0; nt < 4; nt++)
            #pragma unroll
            for (int ks = 0; ks < 4; ks++)
                #pragma unroll
                for (int j = 0; j < 2; j++) {
                    const int ci0 = ks * 16 + j * 8 + 2 * (l & 3);
                    const float w0 = Wg[(size_t)ci0 * 64 + n + nt * 8];
                    const float w1 = Wg[(size_t)(ci0 + 1) * 64 + n + nt * 8];
                    Bhi[nt][ks][j] =
                        (uint32_t)__bfloat16_as_ushort(__float2bfloat16(w0))
                      | ((uint32_t)__bfloat16_as_ushort(__float2bfloat16(w1)) << 16);
                }
    }

    const uint32_t a_row = (l & 7) + ((l >> 3) & 1) * 8;
    const uint32_t a_kof = ((l >> 4) & 1) * 16;           // bytes
    const uint32_t b_row = nhalf * 32 + (l & 7);
    const uint32_t b_kof = ((l >> 3) & 1) * 16;           // bytes

    const int er = tid >> 3;   // gather entry-in-pass 0..31
    const int g8 = tid & 7;    // ci octet

    // ---- prologue: full gather of first tile into buffer 0 ----
    {
        const int ebase = blockIdx.x * TILE_E;
        #pragma unroll
        for (int p = 0; p < 4; p++) {
            int eg = ebase + p * 32 + er;
            if (eg >= M) eg = M - 1;
            const int irow = __ldg(in_rows + kM + eg);
            const float4* fp = reinterpret_cast<const float4*>(
                feats + (size_t)irow * 64 + g8 * 8);
            sts_pass(smem, 0, p * 32 + er, g8, __ldg(fp), __ldg(fp + 1));
        }
    }
    __syncthreads();

    int cur = 0;
    for (int tile = blockIdx.x; tile < ntiles; tile += GRID_X) {
        const int ebase = tile * TILE_E;
        const int nxt = cur ^ 1;
        const bool havenext = (tile + GRID_X) < ntiles;

        // next tile's gather indices (short-lived; consumed inside k-loop)
        int irw[4];
        if (havenext) {
            const int nbase = ebase + GRID_X * TILE_E;
            #pragma unroll
            for (int p = 0; p < 4; p++) {
                int eg = nbase + p * 32 + er;
                if (eg >= M) eg = M - 1;
                irw[p] = __ldg(in_rows + kM + eg);
            }
        }
        int orw = -1;
        if (tid < TILE_E) {
            const int eg = ebase + tid;
            if (eg < M) orw = __ldg(out_rows + kM + eg);
        }

        float acc[2][4][4];
        #pragma unroll
        for (int s = 0; s < 2; s++)
            #pragma unroll
            for (int nt = 0; nt < 4; nt++)
                #pragma unroll
                for (int r = 0; r < 4; r++) acc[s][nt][r] = 0.f;

        float4 pa[2], pb[2];

        #pragma unroll
        for (int ks = 0; ks < 4; ks++) {
            // issue next-tile gather LDGs for pass ks
            if (havenext) {
                const float4* fp = reinterpret_cast<const float4*>(
                    feats + (size_t)irw[ks] * 64 + g8 * 8);
                pa[ks & 1] = __ldg(fp);
                pb[ks & 1] = __ldg(fp + 1);
            }

            uint32_t blo[4][2];
            #pragma unroll
            for (int nt = 0; nt < 4; nt++) {
                const unsigned bo = (b_row + nt * 8) * 128 + ks * 32 + b_kof;
                LDMX2(blo[nt][0], blo[nt][1], sb + WLO_OFF + SW(bo));
            }

            // convert + store the pass issued last iteration
            if (havenext && ks > 0)
                sts_pass(smem, nxt, (ks - 1) * 32 + er, g8,
                         pa[(ks - 1) & 1], pb[(ks - 1) & 1]);

            #pragma unroll
            for (int s = 0; s < 2; s++) {
                const unsigned ao =
                    (eslab * 32 + s * 16 + a_row) * 128 + ks * 32 + a_kof;
                const unsigned aosw = SW(ao);
                uint32_t ahi[4], alo[4];
                LDMX4(ahi, sb + AHI(cur) + aosw);
                LDMX4(alo, sb + ALO(cur) + aosw);
                #pragma unroll
                for (int nt = 0; nt < 4; nt++) {
                    mma16816(acc[s][nt], ahi, Bhi[nt][ks][0], Bhi[nt][ks][1]);
                    mma16816(acc[s][nt], ahi, blo[nt][0],     blo[nt][1]);
                    mma16816(acc[s][nt], alo, Bhi[nt][ks][0], Bhi[nt][ks][1]);
                }
            }
        }
        if (havenext) sts_pass(smem, nxt, 96 + er, g8, pa[1], pb[1]);

        // ---- epilogue ----
        // previous reduces must have READ the stage (not necessarily completed)
        asm volatile("cp.async.bulk.wait_group.read 0;" ::: "memory");
        __syncthreads();   // also: all STS(nxt) done, all ldmatrix(cur) done

        {
            const int r0 = l >> 2;            // 0..7
            const int cb = 2 * (l & 3);       // 0,2,4,6
            float* stg = reinterpret_cast<float*>(smem + STG_OFF);
            #pragma unroll
            for (int s = 0; s < 2; s++) {
                const int eb = eslab * 32 + s * 16;
                #pragma unroll
                for (int nt = 0; nt < 4; nt++) {
                    const int c = nhalf * 32 + nt * 8 + cb;
                    *reinterpret_cast<float2*>(&stg[(eb + r0) * 68 + c]) =
                        make_float2(acc[s][nt][0], acc[s][nt][1]);
                    *reinterpret_cast<float2*>(&stg[(eb + r0 + 8) * 68 + c]) =
                        make_float2(acc[s][nt][2], acc[s][nt][3]);
                }
            }
        }
        asm volatile("fence.proxy.async.shared::cta;" ::: "memory");
        __syncthreads();

        if (orw >= 0) {
            const float* dst = out + (size_t)orw * 64;
            const uint32_t src = sb + STG_OFF + tid * 272;
            asm volatile(
                "cp.reduce.async.bulk.global.shared::cta.bulk_group.add.f32 "
                "[%0], [%1], 256;"
                :: "l"(dst), "r"(src) : "memory");
        }
        asm volatile("cp.async.bulk.commit_group;" ::: "memory");

        cur = nxt;
    }

    asm volatile("cp.async.bulk.wait_group 0;" ::: "memory");
}

extern "C" void kernel_launch(void* const* d_in, const int* in_sizes, int n_in,
                              void* d_out, int out_size) {
    const int*   coords   = (const int*)  d_in[0];
    const float* feats    = (const float*)d_in[1];
    const int*   in_rows  = (const int*)  d_in[2];
    const int*   out_rows = (const int*)  d_in[3];
    const float* weight   = (const float*)d_in[4];
    const float* bias     = (const float*)d_in[5];

    const int N = in_sizes[1] / 64;   // feats is [N, 64]
    const int M = in_sizes[2] / 9;    // in_rows is [9, M]

    // d_out is float32: [ float(coords) | out[N,64] ]
    float* outf = (float*)d_out;
    long coords_elems = (long)out_size - (long)N * 64;
    if (coords_elems < 0) coords_elems = 0;
    if (coords_elems > in_sizes[0]) coords_elems = in_sizes[0];
    float* out = outf + coords_elems;

    const int total4 = N * 16;
    const int nc4    = (int)(coords_elems / 4);
    const int tot    = total4 + nc4;
    vsc_prep<<<(tot + 255) / 256, 256>>>(
        (float4*)out, (const float4*)bias, total4,
        (const int4*)coords, (float4*)outf, nc4);

    cudaFuncSetAttribute(vsc_mma, cudaFuncAttributeMaxDynamicSharedMemorySize,
                         SMEM_SZ);
    const int ntiles = (M + TILE_E - 1) / TILE_E;
    dim3 grid(GRID_X, 9);
    vsc_mma<<<grid, 256, SMEM_SZ>>>(feats, in_rows, out_rows, weight, out,
                                    M, ntiles);
}